// round 8
// baseline (speedup 1.0000x reference)
#include <cuda_runtime.h>
#include <cuda_fp16.h>
#include <float.h>

#define BB   64
#define DD   64
#define TTm  4096
#define KKm  512
#define TILE 128
#define NTH  256
#define N_ELEM ((size_t)BB * DD * TTm)
#define WINDOW 8e-4f

// smem byte offsets
#define SM_X2    0         // 128 f
#define SM_C2    512       // 512 f
#define SM_KIDX  2560      // 128 i
#define SM_WRED  3072      // 8 f
#define SM_QCNT  3104      // 1 i
#define SM_QUE   3136      // 128 i
#define SM_ZS    3712      // 128x64 f32 [d][t]          (32768 B)
#define SM_ZH    36480     // fp16 [d][t], 256 B rows    (16384 B)
#define SM_EBC   52864     // half2 (e,e) [d][code], 512 B rows (32768 B)
#define SM_TOTAL 85632

__device__ double  g_loss;
__device__ float   g_c2[KKm];
__device__ __half2 g_ebc[DD * KKm];   // [d][k] duplicated (e,e) pairs

// ---------------------------------------------------------------------------
// prep1: c2 (rounded squares + pairwise tree, reference numerics) + loss = 0
// ---------------------------------------------------------------------------
__global__ void vq_prep1(const float* __restrict__ emb) {
    int k = threadIdx.x;
    if (k == 0) g_loss = 0.0;
    if (k < KKm) {
        const float* e = emb + k * DD;
        float p[DD];
        #pragma unroll
        for (int d = 0; d < DD; d++) { float v = e[d]; p[d] = __fmul_rn(v, v); }
        #pragma unroll
        for (int w = DD; w > 1; w >>= 1)
            #pragma unroll
            for (int i = 0; i < DD / 2; i++)
                if (i < w / 2) p[i] = __fadd_rn(p[2 * i], p[2 * i + 1]);
        g_c2[k] = p[0];
    }
}

// prep2: duplicated-pair fp16 codebook, [d][k] layout (coalesced writes)
__global__ void vq_prep2(const float* __restrict__ emb) {
    int gid = blockIdx.x * 256 + threadIdx.x;   // 0..32767
    int d = gid >> 9, k = gid & 511;
    g_ebc[gid] = __float2half2_rn(emb[k * DD + d]);
}

// ---------------------------------------------------------------------------
// main: fp16 HFMA2 approx GEMM + gap-gated exact rescue + fused epilogue
// ---------------------------------------------------------------------------
__global__ __launch_bounds__(NTH, 2)
void vq_main(const float* __restrict__ z, const float* __restrict__ emb,
             float* __restrict__ out) {
    extern __shared__ char smem[];
    const int tid  = threadIdx.x;
    const int wid  = tid >> 5, lane = tid & 31;
    const int tile = blockIdx.x, b = tile >> 5, t0 = (tile & 31) * TILE;
    const size_t zbase = (size_t)b * DD * TTm + t0;

    float* zs   = (float*)(smem + SM_ZS);
    float* x2s  = (float*)(smem + SM_X2);
    float* c2s  = (float*)(smem + SM_C2);
    int*   kidx = (int*)(smem + SM_KIDX);
    float* wred = (float*)(smem + SM_WRED);
    int*   qcnt = (int*)(smem + SM_QCNT);
    int*   que  = (int*)(smem + SM_QUE);

    if (tid == 0) *qcnt = 0;

    // ---- load z tile fp32 [d][t] coalesced; c2 ----
    for (int i = tid; i < DD * TILE / 4; i += NTH) {
        int row = i >> 5, col = (i & 31) << 2;
        *(float4*)(zs + row * TILE + col) =
            *(const float4*)(z + zbase + (size_t)row * TTm + col);
    }
    for (int i = tid; i < KKm; i += NTH) c2s[i] = g_c2[i];
    __syncthreads();

    // ---- build fp16 z tile [d][t], 256B rows ----
    for (int i = tid; i < DD * TILE / 2; i += NTH) {
        int d = i >> 6, tp = i & 63;
        float2 zz = *(const float2*)(zs + d * TILE + tp * 2);
        *(__half2*)(smem + SM_ZH + d * 256 + tp * 4) = __floats2half2_rn(zz.x, zz.y);
    }
    // ---- per-token ||x||^2 (exact fp32 chain) ----
    if (tid < TILE) {
        float s = 0.f;
        #pragma unroll
        for (int d = 0; d < DD; d++) { float v = zs[d * TILE + tid]; s = fmaf(v, v, s); }
        x2s[tid] = s;
    }

    // per-token (min, argmin, 2nd-min); warp wid owns tokens wid*16..+15
    float d1[16], d2[16]; int k1[16];
    #pragma unroll
    for (int s = 0; s < 16; s++) { d1[s] = FLT_MAX; d2[s] = FLT_MAX; k1[s] = 0; }

    #pragma unroll 1
    for (int ch = 0; ch < 4; ch++) {            // 4 chunks of 128 codes
        __syncthreads();                         // zh ready / prev chunk consumed
        for (int i = tid; i < 2048; i += NTH) {  // copy ebc chunk: 64 rows x 512B
            int d = i >> 5, o = i & 31;
            *(uint4*)(smem + SM_EBC + d * 512 + o * 16) =
                *(const uint4*)((const char*)g_ebc + d * 2048 + ch * 512 + o * 16);
        }
        __syncthreads();

        __half2 acc[8][4];
        #pragma unroll
        for (int tp = 0; tp < 8; tp++)
            #pragma unroll
            for (int c = 0; c < 4; c++) acc[tp][c] = __float2half2_rn(0.f);

        #pragma unroll 4
        for (int d = 0; d < DD; d++) {
            __half2 zv[8], ev[4];
            *(uint4*)&zv[0] = *(const uint4*)(smem + SM_ZH + d * 256 + wid * 32);
            *(uint4*)&zv[4] = *(const uint4*)(smem + SM_ZH + d * 256 + wid * 32 + 16);
            *(uint4*)&ev[0] = *(const uint4*)(smem + SM_EBC + d * 512 + lane * 16);
            #pragma unroll
            for (int c = 0; c < 4; c++)
                #pragma unroll
                for (int tp = 0; tp < 8; tp++)
                    acc[tp][c] = __hfma2(zv[tp], ev[c], acc[tp][c]);
        }

        // fold chunk: dist = c2 - 2*dot (fp32), update (d1,k1,d2)
        #pragma unroll
        for (int c = 0; c < 4; c++) {
            int code = ch * 128 + lane * 4 + c;
            float c2v = c2s[code];
            #pragma unroll
            for (int tp = 0; tp < 8; tp++) {
                float2 f = __half22float2(acc[tp][c]);
                float v0 = fmaf(-2.f, f.x, c2v);
                float v1 = fmaf(-2.f, f.y, c2v);
                int s0 = 2 * tp, s1 = 2 * tp + 1;
                if (v0 < d1[s0]) { d2[s0] = d1[s0]; d1[s0] = v0; k1[s0] = code; }
                else if (v0 < d2[s0]) d2[s0] = v0;
                if (v1 < d1[s1]) { d2[s1] = d1[s1]; d1[s1] = v1; k1[s1] = code; }
                else if (v1 < d2[s1]) d2[s1] = v1;
            }
        }
    }

    // ---- butterfly allreduce of (d1,k1,d2) across the warp's 32 lanes ----
    #pragma unroll
    for (int off = 16; off > 0; off >>= 1) {
        #pragma unroll
        for (int s = 0; s < 16; s++) {
            float od1 = __shfl_xor_sync(0xffffffffu, d1[s], off);
            int   ok1 = __shfl_xor_sync(0xffffffffu, k1[s], off);
            float od2 = __shfl_xor_sync(0xffffffffu, d2[s], off);
            if (od1 < d1[s] || (od1 == d1[s] && ok1 < k1[s])) {
                d2[s] = fminf(d1[s], od2); d1[s] = od1; k1[s] = ok1;
            } else {
                d2[s] = fminf(d2[s], od1);
            }
        }
    }
    if (lane == 0) {
        #pragma unroll
        for (int s = 0; s < 16; s++)
            kidx[wid * 16 + s] = (d2[s] - d1[s] > WINDOW) ? k1[s] : -1;
    }
    __syncthreads();

    // ---- queue ambiguous tokens ----
    if (tid < TILE && kidx[tid] < 0) {
        int pos = atomicAdd(qcnt, 1);
        que[pos] = tid;
    }
    __syncthreads();

    // ---- warp-cooperative exact rescue (reference-rounded, lexicographic) ----
    const int qc = *qcnt;
    for (int q = wid; q < qc; q += NTH / 32) {
        int tok = que[q];
        float x2 = x2s[tok];
        float s[16];
        #pragma unroll
        for (int cc = 0; cc < 16; cc++) s[cc] = 0.f;
        #pragma unroll
        for (int chunk = 0; chunk < 4; chunk++) {
            float zv[16];
            #pragma unroll
            for (int dd = 0; dd < 16; dd++) zv[dd] = zs[(chunk * 16 + dd) * TILE + tok];
            #pragma unroll
            for (int cc = 0; cc < 16; cc++) {
                const float* e = emb + (lane * 16 + cc) * DD + chunk * 16;
                #pragma unroll
                for (int dq = 0; dq < 4; dq++) {
                    float4 ev = __ldg((const float4*)(e + dq * 4));
                    s[cc] = fmaf(zv[dq * 4 + 0], ev.x, s[cc]);
                    s[cc] = fmaf(zv[dq * 4 + 1], ev.y, s[cc]);
                    s[cc] = fmaf(zv[dq * 4 + 2], ev.z, s[cc]);
                    s[cc] = fmaf(zv[dq * 4 + 3], ev.w, s[cc]);
                }
            }
        }
        float bd = FLT_MAX; int bk = 0;
        #pragma unroll
        for (int cc = 0; cc < 16; cc++) {
            int code = lane * 16 + cc;
            float dd = __fsub_rn(__fadd_rn(x2, c2s[code]), __fmul_rn(2.f, s[cc]));
            if (dd < bd) { bd = dd; bk = code; }
        }
        #pragma unroll
        for (int off = 16; off > 0; off >>= 1) {
            float od = __shfl_down_sync(0xffffffffu, bd, off);
            int   ok = __shfl_down_sync(0xffffffffu, bk, off);
            if (od < bd || (od == bd && ok < bk)) { bd = od; bk = ok; }
        }
        if (lane == 0) kidx[tok] = bk;
    }
    __syncthreads();

    // ---- gather + straight-through output + loss (reference rounding) ----
    float lsum = 0.f;
    for (int i = tid; i < DD * TILE; i += NTH) {
        int d = i >> 7, tt = i & 127;
        float q  = __ldg(emb + kidx[tt] * DD + d);
        float zv = zs[d * TILE + tt];
        float diff = __fsub_rn(q, zv);
        out[zbase + (size_t)d * TTm + tt] = __fadd_rn(zv, diff);
        lsum = fmaf(diff, diff, lsum);
    }
    #pragma unroll
    for (int o = 16; o > 0; o >>= 1)
        lsum += __shfl_down_sync(0xffffffffu, lsum, o);
    if (lane == 0) wred[wid] = lsum;
    __syncthreads();
    if (tid == 0) {
        float sacc = 0.f;
        #pragma unroll
        for (int w = 0; w < NTH / 32; w++) sacc += wred[w];
        atomicAdd(&g_loss, (double)sacc);
    }
}

// ---------------------------------------------------------------------------
__global__ void vq_fin(float* __restrict__ out) {
    double m = g_loss / (double)N_ELEM;
    out[N_ELEM]     = (float)m;
    out[N_ELEM + 1] = (float)(0.25 * m);
}

// ---------------------------------------------------------------------------
extern "C" void kernel_launch(void* const* d_in, const int* in_sizes, int n_in,
                              void* d_out, int out_size) {
    const float* z   = (const float*)d_in[0];
    const float* emb = (const float*)d_in[1];
    float*       out = (float*)d_out;

    (void)cudaFuncSetAttribute(vq_main,
                               cudaFuncAttributeMaxDynamicSharedMemorySize,
                               SM_TOTAL);

    vq_prep1<<<1, 512>>>(emb);
    vq_prep2<<<128, 256>>>(emb);
    vq_main<<<(BB * TTm) / TILE, NTH, SM_TOTAL>>>(z, emb, out);
    vq_fin<<<1, 1>>>(out);
}